// round 16
// baseline (speedup 1.0000x reference)
#include <cuda_runtime.h>
#include <cuda_fp16.h>
#include <cstdint>

#define N_NODES 50000
#define N_EDGES 800000
#define HID 64
#define N_GRAPHS 256
#define BN_EPS 1e-5f

// ---------------- scratch (static device globals; no runtime allocation) ----
__device__ __half g_t[(size_t)N_NODES * HID];   // GEMM input, fp16
__device__ __half g_zh[(size_t)N_NODES * HID];  // layer output, fp16
__device__ __half g_xh[(size_t)N_NODES * HID];  // input features, fp16
__device__ int    g_deg[N_NODES];
__device__ int    g_rowptr[N_NODES + 1];        // block-local exclusive prefix
__device__ int    g_bsoff[64];                  // per-1024-block global offsets
__device__ int    g_rank[N_EDGES];              // edge rank within its dst
__device__ int2   g_csr[N_EDGES];               // {src, weight-bits}
__device__ float  g_stats[3 * 128];             // per layer: [sum(64) | sumsq(64)]
__device__ float  g_pooled[N_GRAPHS * HID];
__device__ int    g_bsums[64];
__device__ int    g_done;                       // scan completion counter

// -------- count degrees (rank = atomic return) + convert x to fp16 ----------
__global__ void k_count_xh(const int* __restrict__ ei, const float* __restrict__ x) {
    int e = blockIdx.x * 256 + threadIdx.x;
    if (e < N_EDGES) g_rank[e] = atomicAdd(&g_deg[ei[N_EDGES + e]], 1);
    if (e < (N_NODES * HID) / 16) {
        int base = e * 16;
#pragma unroll
        for (int j = 0; j < 16; j += 2) {
            float2 v = *(const float2*)(x + base + j);
            *(__half2*)(&g_xh[base + j]) = __floats2half2_rn(v.x, v.y);
        }
    }
}

// ---------------- single-kernel prefix scan ----------------------------------
__global__ void k_scan() {
    __shared__ int sm[1024];
    __shared__ int lastflag;
    int t = threadIdx.x, b = blockIdx.x;
    int i = b * 1024 + t;
    int v = (i < N_NODES) ? g_deg[i] : 0;
    if (i < N_NODES) g_deg[i] = 0;            // reset for next call
    sm[t] = v;
    __syncthreads();
    for (int off = 1; off < 1024; off <<= 1) {
        int tmp = (t >= off) ? sm[t - off] : 0;
        __syncthreads();
        sm[t] += tmp;
        __syncthreads();
    }
    if (i <= N_NODES) g_rowptr[i] = sm[t] - v;   // block-local exclusive
    if (t == 1023) g_bsums[b] = sm[1023];

    __threadfence();
    if (t == 0) lastflag = (atomicAdd(&g_done, 1) == (int)gridDim.x - 1);
    __syncthreads();
    if (lastflag) {
        __threadfence();
        int val = (t < (int)gridDim.x) ? g_bsums[t] : 0;
        sm[t] = val;
        __syncthreads();
        for (int off = 1; off < 64; off <<= 1) {
            int tmp = (t >= off) ? sm[t - off] : 0;
            __syncthreads();
            sm[t] += tmp;
            __syncthreads();
        }
        if (t < 64) g_bsoff[t] = (t < (int)gridDim.x) ? (sm[t] - val) : 0;
        if (t == 0) g_done = 0;
    }
}

// ---------------- CSR fill: no atomics (rank precomputed) -------------------
__global__ void k_fill(const int* __restrict__ ei, const float* __restrict__ ew) {
    int e = blockIdx.x * 256 + threadIdx.x;
    if (e < N_EDGES) {
        int dst = ei[N_EDGES + e];
        int p = g_rowptr[dst] + g_bsoff[dst >> 10] + g_rank[e];
        g_csr[p] = make_int2(ei[e], __float_as_int(ew[e]));
    }
}

// ---------------- aggregation: 16 lanes/node, batches of 8 ------------------
// t[node] = a (.) ( z[node] + sum_e w_e z[src_e] ) + c * (1 + sum_e w_e)
// Full batches load unmasked; ONLY the last batch (deg%8 != 0) takes the
// masked path with (src=node, w=0) pads — per-edge selects confined there.
__global__ void k_agg(int prev_stats,
                      const float* __restrict__ gam, const float* __restrict__ bet) {
    const __half* __restrict__ zin = (prev_stats < 0) ? (const __half*)g_xh
                                                      : (const __half*)g_zh;
    int l16 = threadIdx.x & 15;
    int node = (blockIdx.x * blockDim.x + threadIdx.x) >> 4;
    if (node >= N_NODES) return;
    int col = l16 * 4;

    float4 a = make_float4(1.f, 1.f, 1.f, 1.f);
    float4 c = make_float4(0.f, 0.f, 0.f, 0.f);
    if (prev_stats >= 0) {
        const float* st = &g_stats[prev_stats * 128];
        const float inv = 1.0f / (float)N_NODES;
        float4 sm = *(const float4*)&st[col];
        float4 sq = *(const float4*)&st[64 + col];
        float4 gv = *(const float4*)&gam[col];
        float4 bv = *(const float4*)&bet[col];
        float mu;
        mu = sm.x * inv; a.x = rsqrtf(sq.x * inv - mu * mu + BN_EPS) * gv.x; c.x = bv.x - mu * a.x;
        mu = sm.y * inv; a.y = rsqrtf(sq.y * inv - mu * mu + BN_EPS) * gv.y; c.y = bv.y - mu * a.y;
        mu = sm.z * inv; a.z = rsqrtf(sq.z * inv - mu * mu + BN_EPS) * gv.z; c.z = bv.z - mu * a.z;
        mu = sm.w * inv; a.w = rsqrtf(sq.w * inv - mu * mu + BN_EPS) * gv.w; c.w = bv.w - mu * a.w;
    }

    int beg = g_rowptr[node] + g_bsoff[node >> 10];
    int end = g_rowptr[node + 1] + g_bsoff[(node + 1) >> 10];
    int deg = end - beg;
    int nb = (deg + 7) >> 3;
    bool has_rem = (deg & 7) != 0;
    float sx = 0.f, sy = 0.f, sz = 0.f, sw4 = 0.f, wsum = 0.f;

    int2 cw[8];
    if (nb > 0) {
        if (nb == 1 && has_rem) {
#pragma unroll
            for (int j = 0; j < 8; ++j) {
                int idx = beg + j;
                cw[j] = (idx < end) ? g_csr[idx] : make_int2(node, 0);
            }
        } else {
#pragma unroll
            for (int j = 0; j < 8; ++j) cw[j] = g_csr[beg + j];
        }
    }
    for (int b2 = 0; b2 < nb; ++b2) {
        uint2 raw[8];
#pragma unroll
        for (int j = 0; j < 8; ++j)
            raw[j] = *(const uint2*)(zin + (size_t)cw[j].x * HID + col);
        int2 cwn[8];
        if (b2 + 1 < nb) {
            int nb0 = beg + (b2 + 1) * 8;
            if (b2 + 2 == nb && has_rem) {           // next is masked tail
#pragma unroll
                for (int j = 0; j < 8; ++j) {
                    int idx = nb0 + j;
                    cwn[j] = (idx < end) ? g_csr[idx] : make_int2(node, 0);
                }
            } else {                                  // next is full batch
#pragma unroll
                for (int j = 0; j < 8; ++j) cwn[j] = g_csr[nb0 + j];
            }
        }
#pragma unroll
        for (int j = 0; j < 8; ++j) {
            float w = __int_as_float(cw[j].y);
            float2 f01 = __half22float2(*(__half2*)&raw[j].x);
            float2 f23 = __half22float2(*(__half2*)&raw[j].y);
            sx += w * f01.x; sy += w * f01.y; sz += w * f23.x; sw4 += w * f23.y;
            wsum += w;
        }
#pragma unroll
        for (int j = 0; j < 8; ++j) cw[j] = cwn[j];
    }
    wsum += 1.0f;
    uint2 zraw = *(const uint2*)(zin + (size_t)node * HID + col);
    float2 z01 = __half22float2(*(__half2*)&zraw.x);
    float2 z23 = __half22float2(*(__half2*)&zraw.y);
    union { __half2 h[2]; uint2 u; } pk;
    pk.h[0] = __floats2half2_rn(a.x * (z01.x + sx) + c.x * wsum,
                                a.y * (z01.y + sy) + c.y * wsum);
    pk.h[1] = __floats2half2_rn(a.z * (z23.x + sz) + c.z * wsum,
                                a.w * (z23.y + sw4) + c.w * wsum);
    *(uint2*)(&g_t[(size_t)node * HID + col]) = pk.u;
}

// ---------------- fp32 tiled GEMM (64-node tile) + bias + relu + stats ------
__global__ void k_gemm(const float* __restrict__ W, const float* __restrict__ bias,
                       int layer, int do_relu) {
    __shared__ float ts[64][68];      // [node][k], padded
    __shared__ float ws[64 * 64];     // W[k][col]; reused as stats scratch later
    int tid = threadIdx.x;
    int n0 = blockIdx.x * 64;

    for (int i = tid; i < 4096; i += 256) ws[i] = W[i];
#pragma unroll
    for (int it = 0; it < 4; ++it) {
        int li = it * 256 + tid;
        int node = li >> 4, kc = (li & 15) * 4;
        uint2 raw = make_uint2(0u, 0u);
        if (n0 + node < N_NODES)
            raw = *(const uint2*)(g_t + (size_t)(n0 + node) * HID + kc);
        float2 f01 = __half22float2(*(__half2*)&raw.x);
        float2 f23 = __half22float2(*(__half2*)&raw.y);
        *(float4*)&ts[node][kc] = make_float4(f01.x, f01.y, f23.x, f23.y);
    }
    __syncthreads();

    int tx = tid & 15, ty = tid >> 4;
    float acc00=0,acc01=0,acc02=0,acc03=0, acc10=0,acc11=0,acc12=0,acc13=0;
    float acc20=0,acc21=0,acc22=0,acc23=0, acc30=0,acc31=0,acc32=0,acc33=0;
#pragma unroll
    for (int k = 0; k < 64; ++k) {
        float4 wv = *(const float4*)&ws[k * 64 + tx * 4];
        float v0 = ts[ty * 4 + 0][k];
        float v1 = ts[ty * 4 + 1][k];
        float v2 = ts[ty * 4 + 2][k];
        float v3 = ts[ty * 4 + 3][k];
        acc00 += v0*wv.x; acc01 += v0*wv.y; acc02 += v0*wv.z; acc03 += v0*wv.w;
        acc10 += v1*wv.x; acc11 += v1*wv.y; acc12 += v1*wv.z; acc13 += v1*wv.w;
        acc20 += v2*wv.x; acc21 += v2*wv.y; acc22 += v2*wv.z; acc23 += v2*wv.w;
        acc30 += v3*wv.x; acc31 += v3*wv.y; acc32 += v3*wv.z; acc33 += v3*wv.w;
    }

    float4 bv = *(const float4*)&bias[tx * 4];
    float sum0=0,sum1=0,sum2=0,sum3=0, sq0=0,sq1=0,sq2=0,sq3=0;
    float r0[4][4] = {{acc00,acc01,acc02,acc03},{acc10,acc11,acc12,acc13},
                      {acc20,acc21,acc22,acc23},{acc30,acc31,acc32,acc33}};
#pragma unroll
    for (int i = 0; i < 4; ++i) {
        int node = n0 + ty * 4 + i;
        float o0 = r0[i][0] + bv.x, o1 = r0[i][1] + bv.y;
        float o2 = r0[i][2] + bv.z, o3 = r0[i][3] + bv.w;
        if (do_relu) {
            o0 = fmaxf(o0, 0.f); o1 = fmaxf(o1, 0.f);
            o2 = fmaxf(o2, 0.f); o3 = fmaxf(o3, 0.f);
        }
        if (node < N_NODES) {
            union { __half2 h[2]; uint2 u; } pk;
            pk.h[0] = __floats2half2_rn(o0, o1);
            pk.h[1] = __floats2half2_rn(o2, o3);
            *(uint2*)(&g_zh[(size_t)node * HID + tx * 4]) = pk.u;
            sum0 += o0; sum1 += o1; sum2 += o2; sum3 += o3;
            sq0 += o0*o0; sq1 += o1*o1; sq2 += o2*o2; sq3 += o3*o3;
        }
    }

    __syncthreads();
    float* red = ws;
    red[ty * 64 + tx * 4 + 0] = sum0;
    red[ty * 64 + tx * 4 + 1] = sum1;
    red[ty * 64 + tx * 4 + 2] = sum2;
    red[ty * 64 + tx * 4 + 3] = sum3;
    red[1024 + ty * 64 + tx * 4 + 0] = sq0;
    red[1024 + ty * 64 + tx * 4 + 1] = sq1;
    red[1024 + ty * 64 + tx * 4 + 2] = sq2;
    red[1024 + ty * 64 + tx * 4 + 3] = sq3;
    __syncthreads();
    if (tid < 128) {
        int which = tid >> 6, col = tid & 63;
        float S = 0.f;
#pragma unroll
        for (int t2 = 0; t2 < 16; ++t2) S += red[which * 1024 + t2 * 64 + col];
        atomicAdd(&g_stats[layer * 128 + which * 64 + col], S);
    }
}

// ---------------- layer-3 BN + segmented (sorted-batch) pooling -------------
__global__ void k_norm_pool(const float* __restrict__ gam, const float* __restrict__ bet,
                            const int* __restrict__ batch) {
    int col = threadIdx.x & 63;
    int run = blockIdx.x * (blockDim.x >> 6) + (threadIdx.x >> 6);
    int nruns = gridDim.x * (blockDim.x >> 6);
    int per = (N_NODES + nruns - 1) / nruns;
    int r0 = run * per;
    int r1 = min(N_NODES, r0 + per);

    const float* st = &g_stats[2 * 128];
    const float inv = 1.0f / (float)N_NODES;
    float mu = st[col] * inv;
    float var = st[64 + col] * inv - mu * mu;
    float sc = rsqrtf(var + BN_EPS) * gam[col];
    float bb = bet[col];

    int cur = -1;
    float acc = 0.0f;
    for (int n = r0; n < r1; ++n) {
        int gph = batch[n];
        float v = (__half2float(g_zh[(size_t)n * HID + col]) - mu) * sc + bb;
        if (gph != cur) {
            if (cur >= 0) atomicAdd(&g_pooled[cur * HID + col], acc);
            cur = gph;
            acc = v;
        } else {
            acc += v;
        }
    }
    if (cur >= 0) atomicAdd(&g_pooled[cur * HID + col], acc);
}

// ---------------- final MLP + cleanup of g_pooled / g_stats -----------------
__global__ void k_final(const float* __restrict__ fcW1, const float* __restrict__ fcb1,
                        const float* __restrict__ fcW2, const float* __restrict__ fcb2,
                        float* __restrict__ out) {
    __shared__ float wsm[4096];
    __shared__ float b1s[64];
    __shared__ float w2s[64];
    __shared__ float psm[8][64];
    int tid = threadIdx.x;
    for (int i = tid; i < 4096; i += 256) wsm[i] = fcW1[i];
    if (tid < 64) { b1s[tid] = fcb1[tid]; w2s[tid] = fcW2[tid]; }
    __syncthreads();

    int lane = tid & 31, wid = tid >> 5;
    int gph = blockIdx.x * 8 + wid;
    float p0 = fmaxf(g_pooled[gph * HID + lane], 0.f);
    float p1 = fmaxf(g_pooled[gph * HID + lane + 32], 0.f);
    psm[wid][lane] = p0;
    psm[wid][lane + 32] = p1;
    g_pooled[gph * HID + lane] = 0.0f;
    g_pooled[gph * HID + lane + 32] = 0.0f;
    if (blockIdx.x == 0 && tid < 128) {
        g_stats[tid] = 0.0f; g_stats[128 + tid] = 0.0f; g_stats[256 + tid] = 0.0f;
    }
    __syncwarp();

    float h0 = b1s[lane], h1 = b1s[lane + 32];
#pragma unroll
    for (int k = 0; k < 64; ++k) {
        float pk = psm[wid][k];
        h0 += pk * wsm[k * 64 + lane];
        h1 += pk * wsm[k * 64 + lane + 32];
    }
    float part = fmaxf(h0, 0.f) * w2s[lane] + fmaxf(h1, 0.f) * w2s[lane + 32];
#pragma unroll
    for (int off = 16; off >= 1; off >>= 1)
        part += __shfl_xor_sync(0xffffffffu, part, off);
    if (lane == 0) out[gph] = part + fcb2[0];
}

// ---------------- host launcher ---------------------------------------------
extern "C" void kernel_launch(void* const* d_in, const int* in_sizes, int n_in,
                              void* d_out, int out_size) {
    const float* x     = (const float*)d_in[0];
    const int*   ei    = (const int*)d_in[1];
    const float* ew    = (const float*)d_in[2];
    const int*   batch = (const int*)d_in[3];
    const float *W1 = (const float*)d_in[4],  *b1 = (const float*)d_in[5];
    const float *W2 = (const float*)d_in[6],  *b2 = (const float*)d_in[7];
    const float *W3 = (const float*)d_in[8],  *b3 = (const float*)d_in[9];
    const float *fcW1 = (const float*)d_in[10], *fcb1 = (const float*)d_in[11];
    const float *fcW2 = (const float*)d_in[12], *fcb2 = (const float*)d_in[13];
    const float *g1 = (const float*)d_in[14], *be1 = (const float*)d_in[15];
    const float *g2 = (const float*)d_in[16], *be2 = (const float*)d_in[17];
    const float *g3 = (const float*)d_in[18], *be3 = (const float*)d_in[19];
    float* out = (float*)d_out;

    const int EB = (N_EDGES + 255) / 256;              // 3125
    const int NB1024 = (N_NODES + 1023) / 1024;        // 49
    const int AGG_B = (N_NODES * 16 + 255) / 256;      // 3125 (16 lanes/node)
    const int GEMM_B = (N_NODES + 63) / 64;            // 782

    k_count_xh<<<EB, 256>>>(ei, x);                    // our launch 0
    k_scan<<<NB1024, 1024>>>();                        // 1
    k_fill<<<EB, 256>>>(ei, ew);                       // 2

    k_agg<<<AGG_B, 256>>>(-1, nullptr, nullptr);       // 3 (ncu capture slot)
    k_gemm<<<GEMM_B, 256>>>(W1, b1, 0, 1);
    k_agg<<<AGG_B, 256>>>(0, g1, be1);
    k_gemm<<<GEMM_B, 256>>>(W2, b2, 1, 1);
    k_agg<<<AGG_B, 256>>>(1, g2, be2);
    k_gemm<<<GEMM_B, 256>>>(W3, b3, 2, 0);

    k_norm_pool<<<64, 256>>>(g3, be3, batch);
    k_final<<<N_GRAPHS / 8, 256>>>(fcW1, fcb1, fcW2, fcb2, out);
}

// round 17
// speedup vs baseline: 1.0295x; 1.0295x over previous
#include <cuda_runtime.h>
#include <cuda_fp16.h>
#include <cstdint>

#define N_NODES 50000
#define N_EDGES 800000
#define HID 64
#define N_GRAPHS 256
#define BN_EPS 1e-5f

// ---------------- scratch (static device globals; no runtime allocation) ----
__device__ __half g_t[(size_t)N_NODES * HID];   // GEMM input, fp16
__device__ __half g_zh[(size_t)N_NODES * HID];  // layer output, fp16
__device__ __half g_xh[(size_t)N_NODES * HID];  // input features, fp16
__device__ int    g_deg[N_NODES];
__device__ int    g_rowptr[N_NODES + 1];        // block-local exclusive prefix
__device__ int    g_bsoff[64];                  // per-1024-block global offsets
__device__ int    g_rank[N_EDGES];              // edge rank within its dst
__device__ int2   g_csr[N_EDGES];               // {src, weight-bits}
__device__ float  g_stats[3 * 128];             // per layer: [sum(64) | sumsq(64)]
__device__ float  g_pooled[N_GRAPHS * HID];
__device__ int    g_bsums[64];
__device__ int    g_done;                       // scan completion counter

// -------- count degrees (rank = atomic return) + convert x to fp16 ----------
__global__ void k_count_xh(const int* __restrict__ ei, const float* __restrict__ x) {
    int e = blockIdx.x * 256 + threadIdx.x;
    if (e < N_EDGES) g_rank[e] = atomicAdd(&g_deg[ei[N_EDGES + e]], 1);
    if (e < (N_NODES * HID) / 16) {
        int base = e * 16;
#pragma unroll
        for (int j = 0; j < 16; j += 2) {
            float2 v = *(const float2*)(x + base + j);
            *(__half2*)(&g_xh[base + j]) = __floats2half2_rn(v.x, v.y);
        }
    }
}

// ---------------- single-kernel prefix scan ----------------------------------
__global__ void k_scan() {
    __shared__ int sm[1024];
    __shared__ int lastflag;
    int t = threadIdx.x, b = blockIdx.x;
    int i = b * 1024 + t;
    int v = (i < N_NODES) ? g_deg[i] : 0;
    if (i < N_NODES) g_deg[i] = 0;            // reset for next call
    sm[t] = v;
    __syncthreads();
    for (int off = 1; off < 1024; off <<= 1) {
        int tmp = (t >= off) ? sm[t - off] : 0;
        __syncthreads();
        sm[t] += tmp;
        __syncthreads();
    }
    if (i <= N_NODES) g_rowptr[i] = sm[t] - v;   // block-local exclusive
    if (t == 1023) g_bsums[b] = sm[1023];

    __threadfence();
    if (t == 0) lastflag = (atomicAdd(&g_done, 1) == (int)gridDim.x - 1);
    __syncthreads();
    if (lastflag) {
        __threadfence();
        int val = (t < (int)gridDim.x) ? g_bsums[t] : 0;
        sm[t] = val;
        __syncthreads();
        for (int off = 1; off < 64; off <<= 1) {
            int tmp = (t >= off) ? sm[t - off] : 0;
            __syncthreads();
            sm[t] += tmp;
            __syncthreads();
        }
        if (t < 64) g_bsoff[t] = (t < (int)gridDim.x) ? (sm[t] - val) : 0;
        if (t == 0) g_done = 0;
    }
}

// ---------------- CSR fill: no atomics (rank precomputed) -------------------
__global__ void k_fill(const int* __restrict__ ei, const float* __restrict__ ew) {
    int e = blockIdx.x * 256 + threadIdx.x;
    if (e < N_EDGES) {
        int dst = ei[N_EDGES + e];
        int p = g_rowptr[dst] + g_bsoff[dst >> 10] + g_rank[e];
        g_csr[p] = make_int2(ei[e], __float_as_int(ew[e]));
    }
}

// ---------------- aggregation: 16 lanes/node, masked batches of 8 -----------
// t[node] = a (.) ( z[node] + sum_e w_e z[src_e] ) + c * (1 + sum_e w_e)
// R13 loop structure. BN affine computed AFTER the gather loop (it commutes
// with the sum) so its 8 registers + rsqrt chain are not live in the hot loop.
__global__ void k_agg(int prev_stats,
                      const float* __restrict__ gam, const float* __restrict__ bet) {
    const __half* __restrict__ zin = (prev_stats < 0) ? (const __half*)g_xh
                                                      : (const __half*)g_zh;
    int l16 = threadIdx.x & 15;
    int node = (blockIdx.x * blockDim.x + threadIdx.x) >> 4;
    if (node >= N_NODES) return;
    int col = l16 * 4;

    int beg = g_rowptr[node] + g_bsoff[node >> 10];
    int end = g_rowptr[node + 1] + g_bsoff[(node + 1) >> 10];
    float sx = 0.f, sy = 0.f, sz = 0.f, sw4 = 0.f, wsum = 0.f;

    int nb = (end - beg + 7) >> 3;             // masked batches of 8
    int2 cw[8];
    if (nb > 0) {
#pragma unroll
        for (int j = 0; j < 8; ++j) {
            int idx = beg + j;
            cw[j] = (idx < end) ? g_csr[idx] : make_int2(node, 0);
        }
    }
    for (int b2 = 0; b2 < nb; ++b2) {
        uint2 raw[8];
#pragma unroll
        for (int j = 0; j < 8; ++j)
            raw[j] = *(const uint2*)(zin + (size_t)cw[j].x * HID + col);
        int2 cwn[8];
        if (b2 + 1 < nb) {
            int nb0 = beg + (b2 + 1) * 8;
#pragma unroll
            for (int j = 0; j < 8; ++j) {
                int idx = nb0 + j;
                cwn[j] = (idx < end) ? g_csr[idx] : make_int2(node, 0);
            }
        }
#pragma unroll
        for (int j = 0; j < 8; ++j) {
            float w = __int_as_float(cw[j].y);
            float2 f01 = __half22float2(*(__half2*)&raw[j].x);
            float2 f23 = __half22float2(*(__half2*)&raw[j].y);
            sx += w * f01.x; sy += w * f01.y; sz += w * f23.x; sw4 += w * f23.y;
            wsum += w;
        }
#pragma unroll
        for (int j = 0; j < 8; ++j) cw[j] = cwn[j];
    }
    wsum += 1.0f;

    // BN affine of previous layer, applied post-hoc (identity for layer 1)
    float4 a = make_float4(1.f, 1.f, 1.f, 1.f);
    float4 c = make_float4(0.f, 0.f, 0.f, 0.f);
    if (prev_stats >= 0) {
        const float* st = &g_stats[prev_stats * 128];
        const float inv = 1.0f / (float)N_NODES;
        float4 sm = *(const float4*)&st[col];
        float4 sq = *(const float4*)&st[64 + col];
        float4 gv = *(const float4*)&gam[col];
        float4 bv = *(const float4*)&bet[col];
        float mu;
        mu = sm.x * inv; a.x = rsqrtf(sq.x * inv - mu * mu + BN_EPS) * gv.x; c.x = bv.x - mu * a.x;
        mu = sm.y * inv; a.y = rsqrtf(sq.y * inv - mu * mu + BN_EPS) * gv.y; c.y = bv.y - mu * a.y;
        mu = sm.z * inv; a.z = rsqrtf(sq.z * inv - mu * mu + BN_EPS) * gv.z; c.z = bv.z - mu * a.z;
        mu = sm.w * inv; a.w = rsqrtf(sq.w * inv - mu * mu + BN_EPS) * gv.w; c.w = bv.w - mu * a.w;
    }

    uint2 zraw = *(const uint2*)(zin + (size_t)node * HID + col);
    float2 z01 = __half22float2(*(__half2*)&zraw.x);
    float2 z23 = __half22float2(*(__half2*)&zraw.y);
    union { __half2 h[2]; uint2 u; } pk;
    pk.h[0] = __floats2half2_rn(a.x * (z01.x + sx) + c.x * wsum,
                                a.y * (z01.y + sy) + c.y * wsum);
    pk.h[1] = __floats2half2_rn(a.z * (z23.x + sz) + c.z * wsum,
                                a.w * (z23.y + sw4) + c.w * wsum);
    *(uint2*)(&g_t[(size_t)node * HID + col]) = pk.u;
}

// ---------------- fp32 tiled GEMM (64-node tile) + bias + relu + stats ------
__global__ void k_gemm(const float* __restrict__ W, const float* __restrict__ bias,
                       int layer, int do_relu) {
    __shared__ float ts[64][68];      // [node][k], padded
    __shared__ float ws[64 * 64];     // W[k][col]; reused as stats scratch later
    int tid = threadIdx.x;
    int n0 = blockIdx.x * 64;

    for (int i = tid; i < 4096; i += 256) ws[i] = W[i];
#pragma unroll
    for (int it = 0; it < 4; ++it) {
        int li = it * 256 + tid;
        int node = li >> 4, kc = (li & 15) * 4;
        uint2 raw = make_uint2(0u, 0u);
        if (n0 + node < N_NODES)
            raw = *(const uint2*)(g_t + (size_t)(n0 + node) * HID + kc);
        float2 f01 = __half22float2(*(__half2*)&raw.x);
        float2 f23 = __half22float2(*(__half2*)&raw.y);
        *(float4*)&ts[node][kc] = make_float4(f01.x, f01.y, f23.x, f23.y);
    }
    __syncthreads();

    int tx = tid & 15, ty = tid >> 4;
    float acc00=0,acc01=0,acc02=0,acc03=0, acc10=0,acc11=0,acc12=0,acc13=0;
    float acc20=0,acc21=0,acc22=0,acc23=0, acc30=0,acc31=0,acc32=0,acc33=0;
#pragma unroll
    for (int k = 0; k < 64; ++k) {
        float4 wv = *(const float4*)&ws[k * 64 + tx * 4];
        float v0 = ts[ty * 4 + 0][k];
        float v1 = ts[ty * 4 + 1][k];
        float v2 = ts[ty * 4 + 2][k];
        float v3 = ts[ty * 4 + 3][k];
        acc00 += v0*wv.x; acc01 += v0*wv.y; acc02 += v0*wv.z; acc03 += v0*wv.w;
        acc10 += v1*wv.x; acc11 += v1*wv.y; acc12 += v1*wv.z; acc13 += v1*wv.w;
        acc20 += v2*wv.x; acc21 += v2*wv.y; acc22 += v2*wv.z; acc23 += v2*wv.w;
        acc30 += v3*wv.x; acc31 += v3*wv.y; acc32 += v3*wv.z; acc33 += v3*wv.w;
    }

    float4 bv = *(const float4*)&bias[tx * 4];
    float sum0=0,sum1=0,sum2=0,sum3=0, sq0=0,sq1=0,sq2=0,sq3=0;
    float r0[4][4] = {{acc00,acc01,acc02,acc03},{acc10,acc11,acc12,acc13},
                      {acc20,acc21,acc22,acc23},{acc30,acc31,acc32,acc33}};
#pragma unroll
    for (int i = 0; i < 4; ++i) {
        int node = n0 + ty * 4 + i;
        float o0 = r0[i][0] + bv.x, o1 = r0[i][1] + bv.y;
        float o2 = r0[i][2] + bv.z, o3 = r0[i][3] + bv.w;
        if (do_relu) {
            o0 = fmaxf(o0, 0.f); o1 = fmaxf(o1, 0.f);
            o2 = fmaxf(o2, 0.f); o3 = fmaxf(o3, 0.f);
        }
        if (node < N_NODES) {
            union { __half2 h[2]; uint2 u; } pk;
            pk.h[0] = __floats2half2_rn(o0, o1);
            pk.h[1] = __floats2half2_rn(o2, o3);
            *(uint2*)(&g_zh[(size_t)node * HID + tx * 4]) = pk.u;
            sum0 += o0; sum1 += o1; sum2 += o2; sum3 += o3;
            sq0 += o0*o0; sq1 += o1*o1; sq2 += o2*o2; sq3 += o3*o3;
        }
    }

    __syncthreads();
    float* red = ws;
    red[ty * 64 + tx * 4 + 0] = sum0;
    red[ty * 64 + tx * 4 + 1] = sum1;
    red[ty * 64 + tx * 4 + 2] = sum2;
    red[ty * 64 + tx * 4 + 3] = sum3;
    red[1024 + ty * 64 + tx * 4 + 0] = sq0;
    red[1024 + ty * 64 + tx * 4 + 1] = sq1;
    red[1024 + ty * 64 + tx * 4 + 2] = sq2;
    red[1024 + ty * 64 + tx * 4 + 3] = sq3;
    __syncthreads();
    if (tid < 128) {
        int which = tid >> 6, col = tid & 63;
        float S = 0.f;
#pragma unroll
        for (int t2 = 0; t2 < 16; ++t2) S += red[which * 1024 + t2 * 64 + col];
        atomicAdd(&g_stats[layer * 128 + which * 64 + col], S);
    }
}

// ---------------- layer-3 BN + segmented (sorted-batch) pooling -------------
__global__ void k_norm_pool(const float* __restrict__ gam, const float* __restrict__ bet,
                            const int* __restrict__ batch) {
    int col = threadIdx.x & 63;
    int run = blockIdx.x * (blockDim.x >> 6) + (threadIdx.x >> 6);
    int nruns = gridDim.x * (blockDim.x >> 6);
    int per = (N_NODES + nruns - 1) / nruns;
    int r0 = run * per;
    int r1 = min(N_NODES, r0 + per);

    const float* st = &g_stats[2 * 128];
    const float inv = 1.0f / (float)N_NODES;
    float mu = st[col] * inv;
    float var = st[64 + col] * inv - mu * mu;
    float sc = rsqrtf(var + BN_EPS) * gam[col];
    float bb = bet[col];

    int cur = -1;
    float acc = 0.0f;
    for (int n = r0; n < r1; ++n) {
        int gph = batch[n];
        float v = (__half2float(g_zh[(size_t)n * HID + col]) - mu) * sc + bb;
        if (gph != cur) {
            if (cur >= 0) atomicAdd(&g_pooled[cur * HID + col], acc);
            cur = gph;
            acc = v;
        } else {
            acc += v;
        }
    }
    if (cur >= 0) atomicAdd(&g_pooled[cur * HID + col], acc);
}

// ---------------- final MLP + cleanup of g_pooled / g_stats -----------------
__global__ void k_final(const float* __restrict__ fcW1, const float* __restrict__ fcb1,
                        const float* __restrict__ fcW2, const float* __restrict__ fcb2,
                        float* __restrict__ out) {
    __shared__ float wsm[4096];
    __shared__ float b1s[64];
    __shared__ float w2s[64];
    __shared__ float psm[8][64];
    int tid = threadIdx.x;
    for (int i = tid; i < 4096; i += 256) wsm[i] = fcW1[i];
    if (tid < 64) { b1s[tid] = fcb1[tid]; w2s[tid] = fcW2[tid]; }
    __syncthreads();

    int lane = tid & 31, wid = tid >> 5;
    int gph = blockIdx.x * 8 + wid;
    float p0 = fmaxf(g_pooled[gph * HID + lane], 0.f);
    float p1 = fmaxf(g_pooled[gph * HID + lane + 32], 0.f);
    psm[wid][lane] = p0;
    psm[wid][lane + 32] = p1;
    g_pooled[gph * HID + lane] = 0.0f;
    g_pooled[gph * HID + lane + 32] = 0.0f;
    if (blockIdx.x == 0 && tid < 128) {
        g_stats[tid] = 0.0f; g_stats[128 + tid] = 0.0f; g_stats[256 + tid] = 0.0f;
    }
    __syncwarp();

    float h0 = b1s[lane], h1 = b1s[lane + 32];
#pragma unroll
    for (int k = 0; k < 64; ++k) {
        float pk = psm[wid][k];
        h0 += pk * wsm[k * 64 + lane];
        h1 += pk * wsm[k * 64 + lane + 32];
    }
    float part = fmaxf(h0, 0.f) * w2s[lane] + fmaxf(h1, 0.f) * w2s[lane + 32];
#pragma unroll
    for (int off = 16; off >= 1; off >>= 1)
        part += __shfl_xor_sync(0xffffffffu, part, off);
    if (lane == 0) out[gph] = part + fcb2[0];
}

// ---------------- host launcher ---------------------------------------------
extern "C" void kernel_launch(void* const* d_in, const int* in_sizes, int n_in,
                              void* d_out, int out_size) {
    const float* x     = (const float*)d_in[0];
    const int*   ei    = (const int*)d_in[1];
    const float* ew    = (const float*)d_in[2];
    const int*   batch = (const int*)d_in[3];
    const float *W1 = (const float*)d_in[4],  *b1 = (const float*)d_in[5];
    const float *W2 = (const float*)d_in[6],  *b2 = (const float*)d_in[7];
    const float *W3 = (const float*)d_in[8],  *b3 = (const float*)d_in[9];
    const float *fcW1 = (const float*)d_in[10], *fcb1 = (const float*)d_in[11];
    const float *fcW2 = (const float*)d_in[12], *fcb2 = (const float*)d_in[13];
    const float *g1 = (const float*)d_in[14], *be1 = (const float*)d_in[15];
    const float *g2 = (const float*)d_in[16], *be2 = (const float*)d_in[17];
    const float *g3 = (const float*)d_in[18], *be3 = (const float*)d_in[19];
    float* out = (float*)d_out;

    const int EB = (N_EDGES + 255) / 256;              // 3125
    const int NB1024 = (N_NODES + 1023) / 1024;        // 49
    const int AGG_B = (N_NODES * 16 + 255) / 256;      // 3125 (16 lanes/node)
    const int GEMM_B = (N_NODES + 63) / 64;            // 782

    k_count_xh<<<EB, 256>>>(ei, x);                    // our launch 0
    k_scan<<<NB1024, 1024>>>();                        // 1
    k_fill<<<EB, 256>>>(ei, ew);                       // 2

    k_agg<<<AGG_B, 256>>>(-1, nullptr, nullptr);       // 3 (ncu capture slot)
    k_gemm<<<GEMM_B, 256>>>(W1, b1, 0, 1);
    k_agg<<<AGG_B, 256>>>(0, g1, be1);
    k_gemm<<<GEMM_B, 256>>>(W2, b2, 1, 1);
    k_agg<<<AGG_B, 256>>>(1, g2, be2);
    k_gemm<<<GEMM_B, 256>>>(W3, b3, 2, 0);

    k_norm_pool<<<64, 256>>>(g3, be3, batch);
    k_final<<<N_GRAPHS / 8, 256>>>(fcW1, fcb1, fcW2, fcb2, out);
}